// round 15
// baseline (speedup 1.0000x reference)
#include <cuda_runtime.h>
#include <cstdint>
#include <stdint.h>
#include <cuda_fp16.h>
#include <mma.h>
#include <math.h>

#define LSEQ 2048
#define HID  3072
#define NH   24
#define HD   128
#define MLPD 12288
#define W1N  21504   // 3*HID + MLP
#define QKVN 9216    // 3*HID
#define CATN 15360   // HID + MLP
#define SPLITK 3
#define KSPLIT (CATN / SPLITK)   // 5120

// ---------------- scratch (device globals; no allocations allowed) ----------
__device__ float  g_mod[3 * HID];
__device__ __half g_xmod[(size_t)LSEQ * HID];
__device__ __half g_h[(size_t)LSEQ * QKVN];          // qkv part only, fp16
__device__ __half g_q[(size_t)NH * LSEQ * HD];       // pre-scaled by D^-0.5
__device__ __half g_k[(size_t)NH * LSEQ * HD];
__device__ __half g_v[(size_t)NH * LSEQ * HD];
__device__ __half g_cat[(size_t)LSEQ * CATN];
__device__ __half g_w1h[(size_t)HID * W1N];
__device__ __half g_w2h[(size_t)CATN * HID];
__device__ float  g_part[(size_t)SPLITK * LSEQ * HID];   // split-K partials

// ---------------- async-copy / mma helpers -----------------------------------
__device__ __forceinline__ void cp16(unsigned dst, const void* src) {
    asm volatile("cp.async.cg.shared.global [%0], [%1], 16;\n" :: "r"(dst), "l"(src));
}
__device__ __forceinline__ void cp_commit() {
    asm volatile("cp.async.commit_group;\n");
}
__device__ __forceinline__ void cp_wait0() {
    asm volatile("cp.async.wait_group 0;\n");
}
__device__ __forceinline__ void cp_wait1() {
    asm volatile("cp.async.wait_group 1;\n");
}
__device__ __forceinline__ unsigned saddr(const void* p) {
    return (unsigned)__cvta_generic_to_shared(p);
}
__device__ __forceinline__ void ldsm4(uint32_t& r0, uint32_t& r1, uint32_t& r2,
                                      uint32_t& r3, unsigned addr) {
    asm volatile("ldmatrix.sync.aligned.m8n8.x4.shared.b16 {%0,%1,%2,%3}, [%4];"
                 : "=r"(r0), "=r"(r1), "=r"(r2), "=r"(r3) : "r"(addr));
}
__device__ __forceinline__ void ldsm4t(uint32_t& r0, uint32_t& r1, uint32_t& r2,
                                       uint32_t& r3, unsigned addr) {
    asm volatile("ldmatrix.sync.aligned.m8n8.x4.trans.shared.b16 {%0,%1,%2,%3}, [%4];"
                 : "=r"(r0), "=r"(r1), "=r"(r2), "=r"(r3) : "r"(addr));
}
__device__ __forceinline__ void mma16816(float* d, const uint32_t* a,
                                         uint32_t b0, uint32_t b1) {
    asm volatile(
        "mma.sync.aligned.m16n8k16.row.col.f32.f16.f16.f32 "
        "{%0,%1,%2,%3}, {%4,%5,%6,%7}, {%8,%9}, {%0,%1,%2,%3};\n"
        : "+f"(d[0]), "+f"(d[1]), "+f"(d[2]), "+f"(d[3])
        : "r"(a[0]), "r"(a[1]), "r"(a[2]), "r"(a[3]), "r"(b0), "r"(b1));
}
// f16-accumulator mma with C=0; caller promotes D into fp32 accumulators.
__device__ __forceinline__ void mma16816_h(uint32_t* d, const uint32_t* a,
                                           uint32_t b0, uint32_t b1) {
    uint32_t z = 0;
    asm volatile(
        "mma.sync.aligned.m16n8k16.row.col.f16.f16.f16.f16 "
        "{%0,%1}, {%2,%3,%4,%5}, {%6,%7}, {%8,%9};\n"
        : "=r"(d[0]), "=r"(d[1])
        : "r"(a[0]), "r"(a[1]), "r"(a[2]), "r"(a[3]), "r"(b0), "r"(b1),
          "r"(z), "r"(z));
}
__device__ __forceinline__ uint32_t packh2(float x, float y) {
    __half2 h = __floats2half2_rn(x, y);
    return *reinterpret_cast<uint32_t*>(&h);
}

// ---------------- 0) fp32 -> fp16 weight conversion --------------------------
__global__ void k_convert_h(const float* __restrict__ in, __half* __restrict__ out,
                            size_t n8) {
    const float4* in4 = reinterpret_cast<const float4*>(in);
    uint4* out4 = reinterpret_cast<uint4*>(out);
    for (size_t i = (size_t)blockIdx.x * 256 + threadIdx.x; i < n8;
         i += (size_t)gridDim.x * 256) {
        float4 a = in4[2 * i], b = in4[2 * i + 1];
        __half2 h0 = __floats2half2_rn(a.x, a.y);
        __half2 h1 = __floats2half2_rn(a.z, a.w);
        __half2 h2 = __floats2half2_rn(b.x, b.y);
        __half2 h3 = __floats2half2_rn(b.z, b.w);
        uint4 o;
        o.x = *reinterpret_cast<unsigned*>(&h0);
        o.y = *reinterpret_cast<unsigned*>(&h1);
        o.z = *reinterpret_cast<unsigned*>(&h2);
        o.w = *reinterpret_cast<unsigned*>(&h3);
        out4[i] = o;
    }
}

// ---------------- 1) mod = silu(vec) @ mod_w + mod_b ------------------------
__global__ void k_mod_gemv(const float* __restrict__ vec,
                           const float* __restrict__ mw,
                           const float* __restrict__ mb) {
    __shared__ float sv[HID];
    int tid = threadIdx.x;
    for (int i = tid; i < HID; i += 256) {
        float v = vec[i];
        sv[i] = v / (1.f + expf(-v));
    }
    __syncthreads();
    int j = tid & 63, ky = tid >> 6;
    int col = blockIdx.x * 64 + j;
    const float* wp = mw + col;
    float acc = 0.f;
    int i0 = ky * 768;
#pragma unroll 4
    for (int i = i0; i < i0 + 768; ++i)
        acc += sv[i] * wp[(size_t)i * (3 * HID)];
    __shared__ float red[4][64];
    red[ky][j] = acc;
    __syncthreads();
    if (ky == 0)
        g_mod[col] = red[0][j] + red[1][j] + red[2][j] + red[3][j] + mb[col];
}

// ---------------- 2) LayerNorm + modulate (writes fp16) ----------------------
__global__ void k_ln_mod(const float* __restrict__ x,
                         const float* __restrict__ gamma,
                         const float* __restrict__ beta) {
    int l = blockIdx.x;
    const float* xr = x + (size_t)l * HID;
    float s = 0.f, ss = 0.f;
    for (int c = threadIdx.x; c < HID; c += 256) {
        float v = xr[c];
        s += v; ss += v * v;
    }
    __shared__ float rs[8], rss[8];
    for (int o = 16; o > 0; o >>= 1) {
        s  += __shfl_xor_sync(~0u, s, o);
        ss += __shfl_xor_sync(~0u, ss, o);
    }
    int w = threadIdx.x >> 5;
    if ((threadIdx.x & 31) == 0) { rs[w] = s; rss[w] = ss; }
    __syncthreads();
    float S = 0.f, SS = 0.f;
#pragma unroll
    for (int i = 0; i < 8; ++i) { S += rs[i]; SS += rss[i]; }
    float mu   = S * (1.f / HID);
    float var  = SS * (1.f / HID) - mu * mu;
    float rstd = rsqrtf(var + 1e-6f);
    __half* o = g_xmod + (size_t)l * HID;
    for (int c = threadIdx.x; c < HID; c += 256) {
        float ln = (xr[c] - mu) * rstd * gamma[c] + beta[c];
        o[c] = __float2half_rn((1.f + g_mod[HID + c]) * ln + g_mod[c]);
    }
}

// ---------------- FP16 GEMM: raw mma + ldmatrix, 128x128, BK=32, 3-stage -----
// f16-accumulate per mma (C=0), promoted to fp32 accumulators each step.
// mode 0: C = A@B + b1; cols < QKVN -> g_h (fp16); cols >= QKVN -> gelu -> g_cat
// mode 2: split-K partial: raw acc (no bias) -> f_out + blockIdx.z*LSEQ*HID
#define BM 128
#define BN 128
#define BK 32
#define NSTG 3
#define AS_H 40
#define BS_H 136
#define STG_A (BM * AS_H)
#define STG_B (BK * BS_H)
#define GEMM_DSMEM (NSTG * (STG_A + STG_B) * 2)

__global__ void __launch_bounds__(256, 2) k_gemm(
    const __half* __restrict__ A, int lda,
    const __half* __restrict__ B, int ldb, int K,
    const float* __restrict__ bias, int mode,
    float* __restrict__ f_out) {
    extern __shared__ __half hsm[];

    int tid = threadIdx.x;
    int m0 = blockIdx.x * BM, n0 = blockIdx.y * BN;
    if (mode == 2) {
        int kz = blockIdx.z;
        A += (size_t)kz * KSPLIT;
        B += (size_t)kz * KSPLIT * ldb;
        f_out += (size_t)kz * LSEQ * HID;
    }
    int w = tid >> 5, lane = tid & 31;
    int wm = w & 3, wn = w >> 2;   // warp tile 32x64

    int ar = tid >> 1, ac = (tid & 1) * 16;
    int br = tid >> 3, bc = (tid & 7) * 16;

    int lm = lane >> 3, lr = lane & 7;
    int fr = lane >> 2, fc = (lane & 3) * 2;

    float acc[2][8][4];
#pragma unroll
    for (int i = 0; i < 2; ++i)
#pragma unroll
        for (int c = 0; c < 8; ++c)
#pragma unroll
            for (int j = 0; j < 4; ++j) acc[i][c][j] = 0.f;

    int nsteps = K / BK;
    auto issue = [&](int s) {
        int k0 = s * BK;
        __half* As = hsm + (s % NSTG) * (STG_A + STG_B);
        __half* Bs = As + STG_A;
        {
            const __half* src = A + (size_t)(m0 + ar) * lda + k0 + ac;
            unsigned dst = saddr(As + ar * AS_H + ac);
            cp16(dst, src);
            cp16(dst + 16, src + 8);
        }
        {
            const __half* src = B + (size_t)(k0 + br) * ldb + n0 + bc;
            unsigned dst = saddr(Bs + br * BS_H + bc);
            cp16(dst, src);
            cp16(dst + 16, src + 8);
        }
    };

    issue(0); cp_commit();
    issue(1); cp_commit();

    for (int s = 0; s < nsteps; ++s) {
        if (s + 1 < nsteps) cp_wait1(); else cp_wait0();
        __syncthreads();
        if (s + 2 < nsteps) { issue(s + 2); cp_commit(); }
        __half* As = hsm + (s % NSTG) * (STG_A + STG_B);
        __half* Bs = As + STG_A;
        unsigned abase = saddr(As), bbase = saddr(Bs);
#pragma unroll
        for (int kt = 0; kt < 2; ++kt) {
            int kk = kt * 16;
            uint32_t a[2][4];
#pragma unroll
            for (int i = 0; i < 2; ++i) {
                unsigned addr = abase +
                    ((wm * 32 + i * 16 + (lm & 1) * 8 + lr) * AS_H + kk + (lm >> 1) * 8) * 2;
                ldsm4(a[i][0], a[i][1], a[i][2], a[i][3], addr);
            }
            uint32_t b[8][2];
#pragma unroll
            for (int bw = 0; bw < 4; ++bw) {
                unsigned addr = bbase +
                    ((kk + (lm & 1) * 8 + lr) * BS_H + wn * 64 + bw * 16 + (lm >> 1) * 8) * 2;
                uint32_t r0, r1, r2, r3;
                ldsm4t(r0, r1, r2, r3, addr);
                b[2 * bw][0] = r0; b[2 * bw][1] = r1;
                b[2 * bw + 1][0] = r2; b[2 * bw + 1][1] = r3;
            }
#pragma unroll
            for (int i = 0; i < 2; ++i)
#pragma unroll
                for (int c = 0; c < 8; ++c) {
                    uint32_t d01[2];
                    mma16816_h(d01, a[i], b[c][0], b[c][1]);
                    float2 lo = __half22float2(*reinterpret_cast<__half2*>(&d01[0]));
                    float2 hi = __half22float2(*reinterpret_cast<__half2*>(&d01[1]));
                    acc[i][c][0] += lo.x; acc[i][c][1] += lo.y;
                    acc[i][c][2] += hi.x; acc[i][c][3] += hi.y;
                }
        }
    }

    // epilogue
    bool isgelu = (mode == 0) && (n0 >= QKVN);
#pragma unroll
    for (int i = 0; i < 2; ++i) {
        int gm0 = m0 + wm * 32 + i * 16 + fr;
        int gm1 = gm0 + 8;
#pragma unroll
        for (int c = 0; c < 8; ++c) {
            int gn = n0 + wn * 64 + c * 8 + fc;
            if (mode == 2) {
                float2 o0 = {acc[i][c][0], acc[i][c][1]};
                float2 o1 = {acc[i][c][2], acc[i][c][3]};
                *reinterpret_cast<float2*>(&f_out[(size_t)gm0 * HID + gn]) = o0;
                *reinterpret_cast<float2*>(&f_out[(size_t)gm1 * HID + gn]) = o1;
                continue;
            }
            float b0 = bias[gn], b1 = bias[gn + 1];
            float v00 = acc[i][c][0] + b0, v01 = acc[i][c][1] + b1;
            float v10 = acc[i][c][2] + b0, v11 = acc[i][c][3] + b1;
            if (isgelu) {
                float t, g;
                t = 0.7978845608028654f * (v00 + 0.044715f * v00 * v00 * v00);
                g = 0.5f * v00 * (1.f + tanhf(t)); v00 = g;
                t = 0.7978845608028654f * (v01 + 0.044715f * v01 * v01 * v01);
                g = 0.5f * v01 * (1.f + tanhf(t)); v01 = g;
                t = 0.7978845608028654f * (v10 + 0.044715f * v10 * v10 * v10);
                g = 0.5f * v10 * (1.f + tanhf(t)); v10 = g;
                t = 0.7978845608028654f * (v11 + 0.044715f * v11 * v11 * v11);
                g = 0.5f * v11 * (1.f + tanhf(t)); v11 = g;
                int col = HID + (gn - QKVN);
                *reinterpret_cast<uint32_t*>(&g_cat[(size_t)gm0 * CATN + col]) = packh2(v00, v01);
                *reinterpret_cast<uint32_t*>(&g_cat[(size_t)gm1 * CATN + col]) = packh2(v10, v11);
            } else {
                *reinterpret_cast<uint32_t*>(&g_h[(size_t)gm0 * QKVN + gn]) = packh2(v00, v01);
                *reinterpret_cast<uint32_t*>(&g_h[(size_t)gm1 * QKVN + gn]) = packh2(v10, v11);
            }
        }
    }
}

// ---------------- split-K reduce: out = resid + gate * (p0+p1+p2 + bias) -----
__global__ void k_reduce(float* __restrict__ out,
                         const float* __restrict__ resid,
                         const float* __restrict__ gate,
                         const float* __restrict__ bias) {
    size_t i = (size_t)blockIdx.x * 256 + threadIdx.x;   // float4 index
    size_t total = (size_t)LSEQ * HID / 4;
    if (i >= total) return;
    int col = (int)((i * 4) % HID);
    const float4 p0 = reinterpret_cast<const float4*>(g_part)[i];
    const float4 p1 = reinterpret_cast<const float4*>(g_part + (size_t)LSEQ * HID)[i];
    const float4 p2 = reinterpret_cast<const float4*>(g_part + (size_t)2 * LSEQ * HID)[i];
    float4 r = reinterpret_cast<const float4*>(resid)[i];
    float4 bb = *reinterpret_cast<const float4*>(&bias[col]);
    float4 gg = *reinterpret_cast<const float4*>(&gate[col]);
    float4 o;
    o.x = r.x + gg.x * (p0.x + p1.x + p2.x + bb.x);
    o.y = r.y + gg.y * (p0.y + p1.y + p2.y + bb.y);
    o.z = r.z + gg.z * (p0.z + p1.z + p2.z + bb.z);
    o.w = r.w + gg.w * (p0.w + p1.w + p2.w + bb.w);
    reinterpret_cast<float4*>(out)[i] = o;
}

// ---------------- 3) q/k rmsnorm + rope, v copy; [H][L][D] half --------------
__global__ void k_qkv(const float* __restrict__ pe,
                      const float* __restrict__ qs,
                      const float* __restrict__ ks) {
    int l = blockIdx.x, hh = blockIdx.y, d = threadIdx.x;
    const __half* hrow = g_h + (size_t)l * QKVN;
    float qv = __half2float(hrow[hh * HD + d]);
    float kv = __half2float(hrow[HID + hh * HD + d]);
    float vv = __half2float(hrow[2 * HID + hh * HD + d]);
    float sq = qv * qv, sk = kv * kv;
    for (int o = 16; o > 0; o >>= 1) {
        sq += __shfl_xor_sync(~0u, sq, o);
        sk += __shfl_xor_sync(~0u, sk, o);
    }
    __shared__ float wsq[4], wsk[4];
    int w = d >> 5;
    if ((d & 31) == 0) { wsq[w] = sq; wsk[w] = sk; }
    __syncthreads();
    float msq = (wsq[0] + wsq[1] + wsq[2] + wsq[3]) * (1.f / HD);
    float msk = (wsk[0] + wsk[1] + wsk[2] + wsk[3]) * (1.f / HD);
    __shared__ float nq[HD], nk[HD];
    nq[d] = qv * rsqrtf(msq + 1e-6f) * qs[d];
    nk[d] = kv * rsqrtf(msk + 1e-6f) * ks[d];
    __syncthreads();
    int c = d >> 1, r = d & 1;
    const float* pp = pe + ((size_t)l * 64 + c) * 4 + r * 2;
    float qr = pp[0] * nq[2 * c] + pp[1] * nq[2 * c + 1];
    float kr = pp[0] * nk[2 * c] + pp[1] * nk[2 * c + 1];
    size_t base = ((size_t)hh * LSEQ + l) * HD + d;
    g_q[base] = __float2half_rn(qr * 0.08838834764831845f);  // * D^-0.5
    g_k[base] = __float2half_rn(kr);
    g_v[base] = __float2half_rn(vv);
}

// ---------------- 4) flash attention: 128 q rows/CTA, 8 warps ----------------
#define KS_H 136
#define FA_BUF (64 * KS_H)
#define FA_NSTG 3
#define FA_DSMEM (FA_NSTG * 2 * FA_BUF * 2)
#define NKT (LSEQ / 64)

__global__ void __launch_bounds__(256, 1) k_fattn() {
    extern __shared__ __half fsm[];
    int tid = threadIdx.x, w = tid >> 5, lane = tid & 31;
    int hh = blockIdx.y;
    int q0 = blockIdx.x * 128;
    const __half* Qg = g_q + ((size_t)hh * LSEQ + q0 + w * 16) * HD;
    const __half* Kg = g_k + (size_t)hh * LSEQ * HD;
    const __half* Vg = g_v + (size_t)hh * LSEQ * HD;

    int fr = lane >> 2;
    int fc = (lane & 3) * 2;
    uint32_t qa[8][4];
#pragma unroll
    for (int kc = 0; kc < 8; ++kc) {
        qa[kc][0] = *reinterpret_cast<const uint32_t*>(&Qg[(size_t)fr * HD + kc * 16 + fc]);
        qa[kc][1] = *reinterpret_cast<const uint32_t*>(&Qg[(size_t)(fr + 8) * HD + kc * 16 + fc]);
        qa[kc][2] = *reinterpret_cast<const uint32_t*>(&Qg[(size_t)fr * HD + kc * 16 + 8 + fc]);
        qa[kc][3] = *reinterpret_cast<const uint32_t*>(&Qg[(size_t)(fr + 8) * HD + kc * 16 + 8 + fc]);
    }

    float o[16][4];
#pragma unroll
    for (int c = 0; c < 16; ++c)
#pragma unroll
        for (int j = 0; j < 4; ++j) o[c][j] = 0.f;
    float m0 = -1e30f, m1 = -1e30f, l0 = 0.f, l1 = 0.f;

    int sr = tid >> 2, sc = (tid & 3) * 32;
    auto stg = [&](int t) {
        __half* Ks = fsm + (t % FA_NSTG) * 2 * FA_BUF;
        __half* Vs = Ks + FA_BUF;
        const __half* ksrc = Kg + (size_t)(t * 64 + sr) * HD + sc;
        unsigned kd = saddr(Ks + sr * KS_H + sc);
#pragma unroll
        for (int p = 0; p < 4; ++p) cp16(kd + p * 16, ksrc + p * 8);
        const __half* vsrc = Vg + (size_t)(t * 64 + sr) * HD + sc;
        unsigned vd = saddr(Vs + sr * KS_H + sc);
#pragma unroll
        for (int p = 0; p < 4; ++p) cp16(vd + p * 16, vsrc + p * 8);
    };

    stg(0); cp_commit();
    stg(1); cp_commit();

    int lm = lane >> 3, lr = lane & 7;

    for (int t = 0; t < NKT; ++t) {
        if (t + 1 < NKT) cp_wait1(); else cp_wait0();
        __syncthreads();
        if (t + 2 < NKT) { stg(t + 2); cp_commit(); }
        __half* Ks = fsm + (t % FA_NSTG) * 2 * FA_BUF;
        __half* Vs = Ks + FA_BUF;
        unsigned kbase = saddr(Ks), vbase = saddr(Vs);

        float s[8][4];
#pragma unroll
        for (int c = 0; c < 8; ++c)
#pragma unroll
            for (int j = 0; j < 4; ++j) s[c][j] = 0.f;
#pragma unroll
        for (int kc = 0; kc < 8; ++kc) {
#pragma unroll
            for (int cp = 0; cp < 4; ++cp) {
                unsigned addr = kbase +
                    (((2 * cp + (lm >> 1)) * 8 + lr) * KS_H + kc * 16 + (lm & 1) * 8) * 2;
                uint32_t b0, b1, b2, b3;
                ldsm4(b0, b1, b2, b3, addr);
                mma16816(s[2 * cp], qa[kc], b0, b1);
                mma16816(s[2 * cp + 1], qa[kc], b2, b3);
            }
        }

        float t0 = -1e30f, t1 = -1e30f;
#pragma unroll
        for (int c = 0; c < 8; ++c) {
            t0 = fmaxf(t0, fmaxf(s[c][0], s[c][1]));
            t1 = fmaxf(t1, fmaxf(s[c][2], s[c][3]));
        }
        t0 = fmaxf(t0, __shfl_xor_sync(~0u, t0, 1));
        t0 = fmaxf(t0, __shfl_xor_sync(~0u, t0, 2));
        t1 = fmaxf(t1, __shfl_xor_sync(~0u, t1, 1));
        t1 = fmaxf(t1, __shfl_xor_sync(~0u, t1, 2));
        float mn0 = fmaxf(m0, t0), mn1 = fmaxf(m1, t1);
        float sc0 = __expf(m0 - mn0), sc1 = __expf(m1 - mn1);
        m0 = mn0; m1 = mn1;
        uint32_t ph[8][2];
        float ps0 = 0.f, ps1 = 0.f;
#pragma unroll
        for (int c = 0; c < 8; ++c) {
            float e0 = __expf(s[c][0] - mn0);
            float e1 = __expf(s[c][1] - mn0);
            float e2 = __expf(s[c][2] - mn1);
            float e3 = __expf(s[c][3] - mn1);
            ps0 += e0 + e1; ps1 += e2 + e3;
            ph[c][0] = packh2(e0, e1);
            ph[c][1] = packh2(e2, e3);
        }
        l0 = l0 * sc0 + ps0;
        l1 = l1 * sc1 + ps1;
#pragma unroll
        for (int c = 0; c < 16; ++c) {
            o[c][0] *= sc0; o[c][1] *= sc0;
            o[c][2] *= sc1; o[c][3] *= sc1;
        }

#pragma unroll
        for (int kg = 0; kg < 4; ++kg) {
            uint32_t pa[4] = {ph[2 * kg][0], ph[2 * kg][1],
                              ph[2 * kg + 1][0], ph[2 * kg + 1][1]};
#pragma unroll
            for (int cp = 0; cp < 8; ++cp) {
                unsigned addr = vbase +
                    ((kg * 16 + (lm & 1) * 8 + lr) * KS_H + (2 * cp + (lm >> 1)) * 8) * 2;
                uint32_t b0, b1, b2, b3;
                ldsm4t(b0, b1, b2, b3, addr);
                mma16816(o[2 * cp], pa, b0, b1);
                mma16816(o[2 * cp + 1], pa, b2, b3);
            }
        }
    }

    l0 += __shfl_xor_sync(~0u, l0, 1);
    l0 += __shfl_xor_sync(~0u, l0, 2);
    l1 += __shfl_xor_sync(~0u, l1, 1);
    l1 += __shfl_xor_sync(~0u, l1, 2);
    float il0 = 1.f / l0, il1 = 1.f / l1;
    int row0 = q0 + w * 16 + fr;
    int row1 = row0 + 8;
#pragma unroll
    for (int c = 0; c < 16; ++c) {
        int col = hh * HD + c * 8 + fc;
        *reinterpret_cast<uint32_t*>(&g_cat[(size_t)row0 * CATN + col]) =
            packh2(o[c][0] * il0, o[c][1] * il0);
        *reinterpret_cast<uint32_t*>(&g_cat[(size_t)row1 * CATN + col]) =
            packh2(o[c][2] * il1, o[c][3] * il1);
    }
}

// ---------------- launch -----------------------------------------------------
extern "C" void kernel_launch(void* const* d_in, const int* in_sizes, int n_in,
                              void* d_out, int out_size) {
    const float* x     = (const float*)d_in[0];
    const float* vec   = (const float*)d_in[1];
    const float* pe    = (const float*)d_in[2];
    const float* mod_w = (const float*)d_in[3];
    const float* mod_b = (const float*)d_in[4];
    const float* ln_g  = (const float*)d_in[5];
    const float* ln_b  = (const float*)d_in[6];
    const float* w1    = (const float*)d_in[7];
    const float* b1    = (const float*)d_in[8];
    const float* q_s   = (const float*)d_in[9];
    const float* k_s   = (const float*)d_in[10];
    const float* w2    = (const float*)d_in[11];
    const float* b2    = (const float*)d_in[12];
    float* out = (float*)d_out;

    __half *p_xmod, *p_cat, *p_w1h, *p_w2h;
    float *p_mod, *p_part;
    cudaGetSymbolAddress((void**)&p_xmod, g_xmod);
    cudaGetSymbolAddress((void**)&p_cat,  g_cat);
    cudaGetSymbolAddress((void**)&p_mod,  g_mod);
    cudaGetSymbolAddress((void**)&p_w1h,  g_w1h);
    cudaGetSymbolAddress((void**)&p_w2h,  g_w2h);
    cudaGetSymbolAddress((void**)&p_part, g_part);

    cudaFuncSetAttribute(k_fattn, cudaFuncAttributeMaxDynamicSharedMemorySize,
                         FA_DSMEM);
    cudaFuncSetAttribute(k_gemm, cudaFuncAttributeMaxDynamicSharedMemorySize,
                         GEMM_DSMEM);

    k_mod_gemv<<<144, 256>>>(vec, mod_w, mod_b);                       // 1
    k_convert_h<<<4096, 256>>>(w1, p_w1h, (size_t)HID * W1N / 8);      // 2
    k_ln_mod<<<LSEQ, 256>>>(x, ln_g, ln_b);                            // 3
    // h|gelu(mlp) = x_mod @ w1 + b1       (launch #4 -> profiled)
    k_gemm<<<dim3(16, 168), 256, GEMM_DSMEM>>>(
        p_xmod, HID, p_w1h, W1N, HID, b1, 0, nullptr);
    k_qkv<<<dim3(LSEQ, NH), 128>>>(pe, q_s, k_s);                      // 5
    k_fattn<<<dim3(LSEQ / 128, NH), 256, FA_DSMEM>>>();                // 6
    k_convert_h<<<4096, 256>>>(w2, p_w2h, (size_t)CATN * HID / 8);     // 7
    // split-K=3 partials for cat @ w2
    k_gemm<<<dim3(16, 24, SPLITK), 256, GEMM_DSMEM>>>(
        p_cat, CATN, p_w2h, HID, KSPLIT, nullptr, 2, p_part);
    // out = x + gate * (sum parts + b2)
    k_reduce<<<(LSEQ * HID / 4 + 255) / 256, 256>>>(out, x, p_mod + 2 * HID, b2);
    (void)in_sizes; (void)n_in; (void)out_size;
}

// round 16
// speedup vs baseline: 1.0001x; 1.0001x over previous
#include <cuda_runtime.h>
#include <cstdint>
#include <stdint.h>
#include <cuda_fp16.h>
#include <mma.h>
#include <math.h>

#define LSEQ 2048
#define HID  3072
#define NH   24
#define HD   128
#define MLPD 12288
#define W1N  21504   // 3*HID + MLP
#define QKVN 9216    // 3*HID
#define CATN 15360   // HID + MLP
#define SPLITK 3
#define KSPLIT (CATN / SPLITK)   // 5120

// ---------------- scratch (device globals; no allocations allowed) ----------
__device__ float  g_mod[3 * HID];
__device__ __half g_xmod[(size_t)LSEQ * HID];
__device__ __half g_h[(size_t)LSEQ * QKVN];          // qkv part only, fp16
__device__ __half g_q[(size_t)NH * LSEQ * HD];       // pre-scaled by D^-0.5
__device__ __half g_k[(size_t)NH * LSEQ * HD];
__device__ __half g_v[(size_t)NH * LSEQ * HD];
__device__ __half g_cat[(size_t)LSEQ * CATN];
__device__ __half g_w1h[(size_t)HID * W1N];
__device__ __half g_w2h[(size_t)CATN * HID];
__device__ float  g_part[(size_t)SPLITK * LSEQ * HID];   // split-K partials

// ---------------- async-copy / mma helpers -----------------------------------
__device__ __forceinline__ void cp16(unsigned dst, const void* src) {
    asm volatile("cp.async.cg.shared.global [%0], [%1], 16;\n" :: "r"(dst), "l"(src));
}
__device__ __forceinline__ void cp_commit() {
    asm volatile("cp.async.commit_group;\n");
}
__device__ __forceinline__ void cp_wait0() {
    asm volatile("cp.async.wait_group 0;\n");
}
__device__ __forceinline__ void cp_wait1() {
    asm volatile("cp.async.wait_group 1;\n");
}
__device__ __forceinline__ unsigned saddr(const void* p) {
    return (unsigned)__cvta_generic_to_shared(p);
}
__device__ __forceinline__ void ldsm4(uint32_t& r0, uint32_t& r1, uint32_t& r2,
                                      uint32_t& r3, unsigned addr) {
    asm volatile("ldmatrix.sync.aligned.m8n8.x4.shared.b16 {%0,%1,%2,%3}, [%4];"
                 : "=r"(r0), "=r"(r1), "=r"(r2), "=r"(r3) : "r"(addr));
}
__device__ __forceinline__ void ldsm4t(uint32_t& r0, uint32_t& r1, uint32_t& r2,
                                       uint32_t& r3, unsigned addr) {
    asm volatile("ldmatrix.sync.aligned.m8n8.x4.trans.shared.b16 {%0,%1,%2,%3}, [%4];"
                 : "=r"(r0), "=r"(r1), "=r"(r2), "=r"(r3) : "r"(addr));
}
__device__ __forceinline__ void mma16816(float* d, const uint32_t* a,
                                         uint32_t b0, uint32_t b1) {
    asm volatile(
        "mma.sync.aligned.m16n8k16.row.col.f32.f16.f16.f32 "
        "{%0,%1,%2,%3}, {%4,%5,%6,%7}, {%8,%9}, {%0,%1,%2,%3};\n"
        : "+f"(d[0]), "+f"(d[1]), "+f"(d[2]), "+f"(d[3])
        : "r"(a[0]), "r"(a[1]), "r"(a[2]), "r"(a[3]), "r"(b0), "r"(b1));
}
// f16-accumulator mma with C=0; caller promotes D into fp32 accumulators.
__device__ __forceinline__ void mma16816_h(uint32_t* d, const uint32_t* a,
                                           uint32_t b0, uint32_t b1) {
    uint32_t z = 0;
    asm volatile(
        "mma.sync.aligned.m16n8k16.row.col.f16.f16.f16.f16 "
        "{%0,%1}, {%2,%3,%4,%5}, {%6,%7}, {%8,%9};\n"
        : "=r"(d[0]), "=r"(d[1])
        : "r"(a[0]), "r"(a[1]), "r"(a[2]), "r"(a[3]), "r"(b0), "r"(b1),
          "r"(z), "r"(z));
}
__device__ __forceinline__ uint32_t packh2(float x, float y) {
    __half2 h = __floats2half2_rn(x, y);
    return *reinterpret_cast<uint32_t*>(&h);
}

// ---------------- 0) fp32 -> fp16 weight conversion --------------------------
__global__ void k_convert_h(const float* __restrict__ in, __half* __restrict__ out,
                            size_t n8) {
    const float4* in4 = reinterpret_cast<const float4*>(in);
    uint4* out4 = reinterpret_cast<uint4*>(out);
    for (size_t i = (size_t)blockIdx.x * 256 + threadIdx.x; i < n8;
         i += (size_t)gridDim.x * 256) {
        float4 a = in4[2 * i], b = in4[2 * i + 1];
        __half2 h0 = __floats2half2_rn(a.x, a.y);
        __half2 h1 = __floats2half2_rn(a.z, a.w);
        __half2 h2 = __floats2half2_rn(b.x, b.y);
        __half2 h3 = __floats2half2_rn(b.z, b.w);
        uint4 o;
        o.x = *reinterpret_cast<unsigned*>(&h0);
        o.y = *reinterpret_cast<unsigned*>(&h1);
        o.z = *reinterpret_cast<unsigned*>(&h2);
        o.w = *reinterpret_cast<unsigned*>(&h3);
        out4[i] = o;
    }
}

// ---------------- 1) mod = silu(vec) @ mod_w + mod_b ------------------------
__global__ void k_mod_gemv(const float* __restrict__ vec,
                           const float* __restrict__ mw,
                           const float* __restrict__ mb) {
    __shared__ float sv[HID];
    int tid = threadIdx.x;
    for (int i = tid; i < HID; i += 256) {
        float v = vec[i];
        sv[i] = v / (1.f + expf(-v));
    }
    __syncthreads();
    int j = tid & 63, ky = tid >> 6;
    int col = blockIdx.x * 64 + j;
    const float* wp = mw + col;
    float acc = 0.f;
    int i0 = ky * 768;
#pragma unroll 4
    for (int i = i0; i < i0 + 768; ++i)
        acc += sv[i] * wp[(size_t)i * (3 * HID)];
    __shared__ float red[4][64];
    red[ky][j] = acc;
    __syncthreads();
    if (ky == 0)
        g_mod[col] = red[0][j] + red[1][j] + red[2][j] + red[3][j] + mb[col];
}

// ---------------- 2) LayerNorm + modulate (writes fp16) ----------------------
__global__ void k_ln_mod(const float* __restrict__ x,
                         const float* __restrict__ gamma,
                         const float* __restrict__ beta) {
    int l = blockIdx.x;
    const float* xr = x + (size_t)l * HID;
    float s = 0.f, ss = 0.f;
    for (int c = threadIdx.x; c < HID; c += 256) {
        float v = xr[c];
        s += v; ss += v * v;
    }
    __shared__ float rs[8], rss[8];
    for (int o = 16; o > 0; o >>= 1) {
        s  += __shfl_xor_sync(~0u, s, o);
        ss += __shfl_xor_sync(~0u, ss, o);
    }
    int w = threadIdx.x >> 5;
    if ((threadIdx.x & 31) == 0) { rs[w] = s; rss[w] = ss; }
    __syncthreads();
    float S = 0.f, SS = 0.f;
#pragma unroll
    for (int i = 0; i < 8; ++i) { S += rs[i]; SS += rss[i]; }
    float mu   = S * (1.f / HID);
    float var  = SS * (1.f / HID) - mu * mu;
    float rstd = rsqrtf(var + 1e-6f);
    __half* o = g_xmod + (size_t)l * HID;
    for (int c = threadIdx.x; c < HID; c += 256) {
        float ln = (xr[c] - mu) * rstd * gamma[c] + beta[c];
        o[c] = __float2half_rn((1.f + g_mod[HID + c]) * ln + g_mod[c]);
    }
}

// ---------------- FP16 GEMM: raw mma + ldmatrix, 128x128, BK=32, 3-stage -----
// f16-accumulate per mma (C=0), promoted to fp32 accumulators each step.
// mode 0: C = A@B + b1; cols < QKVN -> g_h (fp16); cols >= QKVN -> gelu -> g_cat
// mode 2: split-K partial: raw acc (no bias) -> f_out + blockIdx.z*LSEQ*HID
#define BM 128
#define BN 128
#define BK 32
#define NSTG 3
#define AS_H 40
#define BS_H 136
#define STG_A (BM * AS_H)
#define STG_B (BK * BS_H)
#define GEMM_DSMEM (NSTG * (STG_A + STG_B) * 2)

__global__ void __launch_bounds__(256, 2) k_gemm(
    const __half* __restrict__ A, int lda,
    const __half* __restrict__ B, int ldb, int K,
    const float* __restrict__ bias, int mode,
    float* __restrict__ f_out) {
    extern __shared__ __half hsm[];

    int tid = threadIdx.x;
    int m0 = blockIdx.x * BM, n0 = blockIdx.y * BN;
    if (mode == 2) {
        int kz = blockIdx.z;
        A += (size_t)kz * KSPLIT;
        B += (size_t)kz * KSPLIT * ldb;
        f_out += (size_t)kz * LSEQ * HID;
    }
    int w = tid >> 5, lane = tid & 31;
    int wm = w & 3, wn = w >> 2;   // warp tile 32x64

    int ar = tid >> 1, ac = (tid & 1) * 16;
    int br = tid >> 3, bc = (tid & 7) * 16;

    int lm = lane >> 3, lr = lane & 7;
    int fr = lane >> 2, fc = (lane & 3) * 2;

    float acc[2][8][4];
#pragma unroll
    for (int i = 0; i < 2; ++i)
#pragma unroll
        for (int c = 0; c < 8; ++c)
#pragma unroll
            for (int j = 0; j < 4; ++j) acc[i][c][j] = 0.f;

    int nsteps = K / BK;
    auto issue = [&](int s) {
        int k0 = s * BK;
        __half* As = hsm + (s % NSTG) * (STG_A + STG_B);
        __half* Bs = As + STG_A;
        {
            const __half* src = A + (size_t)(m0 + ar) * lda + k0 + ac;
            unsigned dst = saddr(As + ar * AS_H + ac);
            cp16(dst, src);
            cp16(dst + 16, src + 8);
        }
        {
            const __half* src = B + (size_t)(k0 + br) * ldb + n0 + bc;
            unsigned dst = saddr(Bs + br * BS_H + bc);
            cp16(dst, src);
            cp16(dst + 16, src + 8);
        }
    };

    issue(0); cp_commit();
    issue(1); cp_commit();

    for (int s = 0; s < nsteps; ++s) {
        if (s + 1 < nsteps) cp_wait1(); else cp_wait0();
        __syncthreads();
        if (s + 2 < nsteps) { issue(s + 2); cp_commit(); }
        __half* As = hsm + (s % NSTG) * (STG_A + STG_B);
        __half* Bs = As + STG_A;
        unsigned abase = saddr(As), bbase = saddr(Bs);
#pragma unroll
        for (int kt = 0; kt < 2; ++kt) {
            int kk = kt * 16;
            uint32_t a[2][4];
#pragma unroll
            for (int i = 0; i < 2; ++i) {
                unsigned addr = abase +
                    ((wm * 32 + i * 16 + (lm & 1) * 8 + lr) * AS_H + kk + (lm >> 1) * 8) * 2;
                ldsm4(a[i][0], a[i][1], a[i][2], a[i][3], addr);
            }
            uint32_t b[8][2];
#pragma unroll
            for (int bw = 0; bw < 4; ++bw) {
                unsigned addr = bbase +
                    ((kk + (lm & 1) * 8 + lr) * BS_H + wn * 64 + bw * 16 + (lm >> 1) * 8) * 2;
                uint32_t r0, r1, r2, r3;
                ldsm4t(r0, r1, r2, r3, addr);
                b[2 * bw][0] = r0; b[2 * bw][1] = r1;
                b[2 * bw + 1][0] = r2; b[2 * bw + 1][1] = r3;
            }
#pragma unroll
            for (int i = 0; i < 2; ++i)
#pragma unroll
                for (int c = 0; c < 8; ++c) {
                    uint32_t d01[2];
                    mma16816_h(d01, a[i], b[c][0], b[c][1]);
                    float2 lo = __half22float2(*reinterpret_cast<__half2*>(&d01[0]));
                    float2 hi = __half22float2(*reinterpret_cast<__half2*>(&d01[1]));
                    acc[i][c][0] += lo.x; acc[i][c][1] += lo.y;
                    acc[i][c][2] += hi.x; acc[i][c][3] += hi.y;
                }
        }
    }

    // epilogue
    bool isgelu = (mode == 0) && (n0 >= QKVN);
#pragma unroll
    for (int i = 0; i < 2; ++i) {
        int gm0 = m0 + wm * 32 + i * 16 + fr;
        int gm1 = gm0 + 8;
#pragma unroll
        for (int c = 0; c < 8; ++c) {
            int gn = n0 + wn * 64 + c * 8 + fc;
            if (mode == 2) {
                float2 o0 = {acc[i][c][0], acc[i][c][1]};
                float2 o1 = {acc[i][c][2], acc[i][c][3]};
                *reinterpret_cast<float2*>(&f_out[(size_t)gm0 * HID + gn]) = o0;
                *reinterpret_cast<float2*>(&f_out[(size_t)gm1 * HID + gn]) = o1;
                continue;
            }
            float b0 = bias[gn], b1 = bias[gn + 1];
            float v00 = acc[i][c][0] + b0, v01 = acc[i][c][1] + b1;
            float v10 = acc[i][c][2] + b0, v11 = acc[i][c][3] + b1;
            if (isgelu) {
                float t, g;
                t = 0.7978845608028654f * (v00 + 0.044715f * v00 * v00 * v00);
                g = 0.5f * v00 * (1.f + tanhf(t)); v00 = g;
                t = 0.7978845608028654f * (v01 + 0.044715f * v01 * v01 * v01);
                g = 0.5f * v01 * (1.f + tanhf(t)); v01 = g;
                t = 0.7978845608028654f * (v10 + 0.044715f * v10 * v10 * v10);
                g = 0.5f * v10 * (1.f + tanhf(t)); v10 = g;
                t = 0.7978845608028654f * (v11 + 0.044715f * v11 * v11 * v11);
                g = 0.5f * v11 * (1.f + tanhf(t)); v11 = g;
                int col = HID + (gn - QKVN);
                *reinterpret_cast<uint32_t*>(&g_cat[(size_t)gm0 * CATN + col]) = packh2(v00, v01);
                *reinterpret_cast<uint32_t*>(&g_cat[(size_t)gm1 * CATN + col]) = packh2(v10, v11);
            } else {
                *reinterpret_cast<uint32_t*>(&g_h[(size_t)gm0 * QKVN + gn]) = packh2(v00, v01);
                *reinterpret_cast<uint32_t*>(&g_h[(size_t)gm1 * QKVN + gn]) = packh2(v10, v11);
            }
        }
    }
}

// ---------------- split-K reduce: out = resid + gate * (p0+p1+p2 + bias) -----
__global__ void k_reduce(float* __restrict__ out,
                         const float* __restrict__ resid,
                         const float* __restrict__ gate,
                         const float* __restrict__ bias) {
    size_t i = (size_t)blockIdx.x * 256 + threadIdx.x;   // float4 index
    size_t total = (size_t)LSEQ * HID / 4;
    if (i >= total) return;
    int col = (int)((i * 4) % HID);
    const float4 p0 = reinterpret_cast<const float4*>(g_part)[i];
    const float4 p1 = reinterpret_cast<const float4*>(g_part + (size_t)LSEQ * HID)[i];
    const float4 p2 = reinterpret_cast<const float4*>(g_part + (size_t)2 * LSEQ * HID)[i];
    float4 r = reinterpret_cast<const float4*>(resid)[i];
    float4 bb = *reinterpret_cast<const float4*>(&bias[col]);
    float4 gg = *reinterpret_cast<const float4*>(&gate[col]);
    float4 o;
    o.x = r.x + gg.x * (p0.x + p1.x + p2.x + bb.x);
    o.y = r.y + gg.y * (p0.y + p1.y + p2.y + bb.y);
    o.z = r.z + gg.z * (p0.z + p1.z + p2.z + bb.z);
    o.w = r.w + gg.w * (p0.w + p1.w + p2.w + bb.w);
    reinterpret_cast<float4*>(out)[i] = o;
}

// ---------------- 3) q/k rmsnorm + rope, v copy; [H][L][D] half --------------
__global__ void k_qkv(const float* __restrict__ pe,
                      const float* __restrict__ qs,
                      const float* __restrict__ ks) {
    int l = blockIdx.x, hh = blockIdx.y, d = threadIdx.x;
    const __half* hrow = g_h + (size_t)l * QKVN;
    float qv = __half2float(hrow[hh * HD + d]);
    float kv = __half2float(hrow[HID + hh * HD + d]);
    float vv = __half2float(hrow[2 * HID + hh * HD + d]);
    float sq = qv * qv, sk = kv * kv;
    for (int o = 16; o > 0; o >>= 1) {
        sq += __shfl_xor_sync(~0u, sq, o);
        sk += __shfl_xor_sync(~0u, sk, o);
    }
    __shared__ float wsq[4], wsk[4];
    int w = d >> 5;
    if ((d & 31) == 0) { wsq[w] = sq; wsk[w] = sk; }
    __syncthreads();
    float msq = (wsq[0] + wsq[1] + wsq[2] + wsq[3]) * (1.f / HD);
    float msk = (wsk[0] + wsk[1] + wsk[2] + wsk[3]) * (1.f / HD);
    __shared__ float nq[HD], nk[HD];
    nq[d] = qv * rsqrtf(msq + 1e-6f) * qs[d];
    nk[d] = kv * rsqrtf(msk + 1e-6f) * ks[d];
    __syncthreads();
    int c = d >> 1, r = d & 1;
    const float* pp = pe + ((size_t)l * 64 + c) * 4 + r * 2;
    float qr = pp[0] * nq[2 * c] + pp[1] * nq[2 * c + 1];
    float kr = pp[0] * nk[2 * c] + pp[1] * nk[2 * c + 1];
    size_t base = ((size_t)hh * LSEQ + l) * HD + d;
    g_q[base] = __float2half_rn(qr * 0.08838834764831845f);  // * D^-0.5
    g_k[base] = __float2half_rn(kr);
    g_v[base] = __float2half_rn(vv);
}

// ---------------- 4) flash attention: 128 q rows/CTA, 8 warps ----------------
#define KS_H 136
#define FA_BUF (64 * KS_H)
#define FA_NSTG 3
#define FA_DSMEM (FA_NSTG * 2 * FA_BUF * 2)
#define NKT (LSEQ / 64)

__global__ void __launch_bounds__(256, 1) k_fattn() {
    extern __shared__ __half fsm[];
    int tid = threadIdx.x, w = tid >> 5, lane = tid & 31;
    int hh = blockIdx.y;
    int q0 = blockIdx.x * 128;
    const __half* Qg = g_q + ((size_t)hh * LSEQ + q0 + w * 16) * HD;
    const __half* Kg = g_k + (size_t)hh * LSEQ * HD;
    const __half* Vg = g_v + (size_t)hh * LSEQ * HD;

    int fr = lane >> 2;
    int fc = (lane & 3) * 2;
    uint32_t qa[8][4];
#pragma unroll
    for (int kc = 0; kc < 8; ++kc) {
        qa[kc][0] = *reinterpret_cast<const uint32_t*>(&Qg[(size_t)fr * HD + kc * 16 + fc]);
        qa[kc][1] = *reinterpret_cast<const uint32_t*>(&Qg[(size_t)(fr + 8) * HD + kc * 16 + fc]);
        qa[kc][2] = *reinterpret_cast<const uint32_t*>(&Qg[(size_t)fr * HD + kc * 16 + 8 + fc]);
        qa[kc][3] = *reinterpret_cast<const uint32_t*>(&Qg[(size_t)(fr + 8) * HD + kc * 16 + 8 + fc]);
    }

    float o[16][4];
#pragma unroll
    for (int c = 0; c < 16; ++c)
#pragma unroll
        for (int j = 0; j < 4; ++j) o[c][j] = 0.f;
    float m0 = -1e30f, m1 = -1e30f, l0 = 0.f, l1 = 0.f;

    int sr = tid >> 2, sc = (tid & 3) * 32;
    auto stg = [&](int t) {
        __half* Ks = fsm + (t % FA_NSTG) * 2 * FA_BUF;
        __half* Vs = Ks + FA_BUF;
        const __half* ksrc = Kg + (size_t)(t * 64 + sr) * HD + sc;
        unsigned kd = saddr(Ks + sr * KS_H + sc);
#pragma unroll
        for (int p = 0; p < 4; ++p) cp16(kd + p * 16, ksrc + p * 8);
        const __half* vsrc = Vg + (size_t)(t * 64 + sr) * HD + sc;
        unsigned vd = saddr(Vs + sr * KS_H + sc);
#pragma unroll
        for (int p = 0; p < 4; ++p) cp16(vd + p * 16, vsrc + p * 8);
    };

    stg(0); cp_commit();
    stg(1); cp_commit();

    int lm = lane >> 3, lr = lane & 7;

    for (int t = 0; t < NKT; ++t) {
        if (t + 1 < NKT) cp_wait1(); else cp_wait0();
        __syncthreads();
        if (t + 2 < NKT) { stg(t + 2); cp_commit(); }
        __half* Ks = fsm + (t % FA_NSTG) * 2 * FA_BUF;
        __half* Vs = Ks + FA_BUF;
        unsigned kbase = saddr(Ks), vbase = saddr(Vs);

        float s[8][4];
#pragma unroll
        for (int c = 0; c < 8; ++c)
#pragma unroll
            for (int j = 0; j < 4; ++j) s[c][j] = 0.f;
#pragma unroll
        for (int kc = 0; kc < 8; ++kc) {
#pragma unroll
            for (int cp = 0; cp < 4; ++cp) {
                unsigned addr = kbase +
                    (((2 * cp + (lm >> 1)) * 8 + lr) * KS_H + kc * 16 + (lm & 1) * 8) * 2;
                uint32_t b0, b1, b2, b3;
                ldsm4(b0, b1, b2, b3, addr);
                mma16816(s[2 * cp], qa[kc], b0, b1);
                mma16816(s[2 * cp + 1], qa[kc], b2, b3);
            }
        }

        float t0 = -1e30f, t1 = -1e30f;
#pragma unroll
        for (int c = 0; c < 8; ++c) {
            t0 = fmaxf(t0, fmaxf(s[c][0], s[c][1]));
            t1 = fmaxf(t1, fmaxf(s[c][2], s[c][3]));
        }
        t0 = fmaxf(t0, __shfl_xor_sync(~0u, t0, 1));
        t0 = fmaxf(t0, __shfl_xor_sync(~0u, t0, 2));
        t1 = fmaxf(t1, __shfl_xor_sync(~0u, t1, 1));
        t1 = fmaxf(t1, __shfl_xor_sync(~0u, t1, 2));
        float mn0 = fmaxf(m0, t0), mn1 = fmaxf(m1, t1);
        float sc0 = __expf(m0 - mn0), sc1 = __expf(m1 - mn1);
        m0 = mn0; m1 = mn1;
        uint32_t ph[8][2];
        float ps0 = 0.f, ps1 = 0.f;
#pragma unroll
        for (int c = 0; c < 8; ++c) {
            float e0 = __expf(s[c][0] - mn0);
            float e1 = __expf(s[c][1] - mn0);
            float e2 = __expf(s[c][2] - mn1);
            float e3 = __expf(s[c][3] - mn1);
            ps0 += e0 + e1; ps1 += e2 + e3;
            ph[c][0] = packh2(e0, e1);
            ph[c][1] = packh2(e2, e3);
        }
        l0 = l0 * sc0 + ps0;
        l1 = l1 * sc1 + ps1;
#pragma unroll
        for (int c = 0; c < 16; ++c) {
            o[c][0] *= sc0; o[c][1] *= sc0;
            o[c][2] *= sc1; o[c][3] *= sc1;
        }

#pragma unroll
        for (int kg = 0; kg < 4; ++kg) {
            uint32_t pa[4] = {ph[2 * kg][0], ph[2 * kg][1],
                              ph[2 * kg + 1][0], ph[2 * kg + 1][1]};
#pragma unroll
            for (int cp = 0; cp < 8; ++cp) {
                unsigned addr = vbase +
                    ((kg * 16 + (lm & 1) * 8 + lr) * KS_H + (2 * cp + (lm >> 1)) * 8) * 2;
                uint32_t b0, b1, b2, b3;
                ldsm4t(b0, b1, b2, b3, addr);
                mma16816(o[2 * cp], pa, b0, b1);
                mma16816(o[2 * cp + 1], pa, b2, b3);
            }
        }
    }

    l0 += __shfl_xor_sync(~0u, l0, 1);
    l0 += __shfl_xor_sync(~0u, l0, 2);
    l1 += __shfl_xor_sync(~0u, l1, 1);
    l1 += __shfl_xor_sync(~0u, l1, 2);
    float il0 = 1.f / l0, il1 = 1.f / l1;
    int row0 = q0 + w * 16 + fr;
    int row1 = row0 + 8;
#pragma unroll
    for (int c = 0; c < 16; ++c) {
        int col = hh * HD + c * 8 + fc;
        *reinterpret_cast<uint32_t*>(&g_cat[(size_t)row0 * CATN + col]) =
            packh2(o[c][0] * il0, o[c][1] * il0);
        *reinterpret_cast<uint32_t*>(&g_cat[(size_t)row1 * CATN + col]) =
            packh2(o[c][2] * il1, o[c][3] * il1);
    }
}

// ---------------- launch -----------------------------------------------------
extern "C" void kernel_launch(void* const* d_in, const int* in_sizes, int n_in,
                              void* d_out, int out_size) {
    const float* x     = (const float*)d_in[0];
    const float* vec   = (const float*)d_in[1];
    const float* pe    = (const float*)d_in[2];
    const float* mod_w = (const float*)d_in[3];
    const float* mod_b = (const float*)d_in[4];
    const float* ln_g  = (const float*)d_in[5];
    const float* ln_b  = (const float*)d_in[6];
    const float* w1    = (const float*)d_in[7];
    const float* b1    = (const float*)d_in[8];
    const float* q_s   = (const float*)d_in[9];
    const float* k_s   = (const float*)d_in[10];
    const float* w2    = (const float*)d_in[11];
    const float* b2    = (const float*)d_in[12];
    float* out = (float*)d_out;

    __half *p_xmod, *p_cat, *p_w1h, *p_w2h;
    float *p_mod, *p_part;
    cudaGetSymbolAddress((void**)&p_xmod, g_xmod);
    cudaGetSymbolAddress((void**)&p_cat,  g_cat);
    cudaGetSymbolAddress((void**)&p_mod,  g_mod);
    cudaGetSymbolAddress((void**)&p_w1h,  g_w1h);
    cudaGetSymbolAddress((void**)&p_w2h,  g_w2h);
    cudaGetSymbolAddress((void**)&p_part, g_part);

    cudaFuncSetAttribute(k_fattn, cudaFuncAttributeMaxDynamicSharedMemorySize,
                         FA_DSMEM);
    cudaFuncSetAttribute(k_gemm, cudaFuncAttributeMaxDynamicSharedMemorySize,
                         GEMM_DSMEM);

    k_mod_gemv<<<144, 256>>>(vec, mod_w, mod_b);                       // 1
    k_convert_h<<<4096, 256>>>(w1, p_w1h, (size_t)HID * W1N / 8);      // 2
    k_ln_mod<<<LSEQ, 256>>>(x, ln_g, ln_b);                            // 3
    // h|gelu(mlp) = x_mod @ w1 + b1       (launch #4 -> profiled)
    k_gemm<<<dim3(16, 168), 256, GEMM_DSMEM>>>(
        p_xmod, HID, p_w1h, W1N, HID, b1, 0, nullptr);
    k_qkv<<<dim3(LSEQ, NH), 128>>>(pe, q_s, k_s);                      // 5
    k_fattn<<<dim3(LSEQ / 128, NH), 256, FA_DSMEM>>>();                // 6
    k_convert_h<<<4096, 256>>>(w2, p_w2h, (size_t)CATN * HID / 8);     // 7
    // split-K=3 partials for cat @ w2
    k_gemm<<<dim3(16, 24, SPLITK), 256, GEMM_DSMEM>>>(
        p_cat, CATN, p_w2h, HID, KSPLIT, nullptr, 2, p_part);
    // out = x + gate * (sum parts + b2)
    k_reduce<<<(LSEQ * HID / 4 + 255) / 256, 256>>>(out, x, p_mod + 2 * HID, b2);
    (void)in_sizes; (void)n_in; (void)out_size;
}

// round 17
// speedup vs baseline: 1.2138x; 1.2136x over previous
#include <cuda_runtime.h>
#include <cstdint>
#include <stdint.h>
#include <cuda_fp16.h>
#include <mma.h>
#include <math.h>

#define LSEQ 2048
#define HID  3072
#define NH   24
#define HD   128
#define MLPD 12288
#define W1N  21504   // 3*HID + MLP
#define QKVN 9216    // 3*HID
#define CATN 15360   // HID + MLP
#define SPLITK 3
#define KSPLIT (CATN / SPLITK)   // 5120

// ---------------- scratch (device globals; no allocations allowed) ----------
__device__ float  g_mod[3 * HID];
__device__ __half g_xmod[(size_t)LSEQ * HID];
__device__ __half g_q[(size_t)NH * LSEQ * HD];       // pre-scaled by D^-0.5
__device__ __half g_k[(size_t)NH * LSEQ * HD];
__device__ __half g_v[(size_t)NH * LSEQ * HD];
__device__ __half g_cat[(size_t)LSEQ * CATN];
__device__ __half g_w1h[(size_t)HID * W1N];
__device__ __half g_w2h[(size_t)CATN * HID];
__device__ float  g_part[(size_t)SPLITK * LSEQ * HID];   // split-K partials

// ---------------- async-copy / mma helpers -----------------------------------
__device__ __forceinline__ void cp16(unsigned dst, const void* src) {
    asm volatile("cp.async.cg.shared.global [%0], [%1], 16;\n" :: "r"(dst), "l"(src));
}
__device__ __forceinline__ void cp_commit() {
    asm volatile("cp.async.commit_group;\n");
}
__device__ __forceinline__ void cp_wait0() {
    asm volatile("cp.async.wait_group 0;\n");
}
__device__ __forceinline__ void cp_wait1() {
    asm volatile("cp.async.wait_group 1;\n");
}
__device__ __forceinline__ unsigned saddr(const void* p) {
    return (unsigned)__cvta_generic_to_shared(p);
}
__device__ __forceinline__ void ldsm4(uint32_t& r0, uint32_t& r1, uint32_t& r2,
                                      uint32_t& r3, unsigned addr) {
    asm volatile("ldmatrix.sync.aligned.m8n8.x4.shared.b16 {%0,%1,%2,%3}, [%4];"
                 : "=r"(r0), "=r"(r1), "=r"(r2), "=r"(r3) : "r"(addr));
}
__device__ __forceinline__ void ldsm4t(uint32_t& r0, uint32_t& r1, uint32_t& r2,
                                       uint32_t& r3, unsigned addr) {
    asm volatile("ldmatrix.sync.aligned.m8n8.x4.trans.shared.b16 {%0,%1,%2,%3}, [%4];"
                 : "=r"(r0), "=r"(r1), "=r"(r2), "=r"(r3) : "r"(addr));
}
__device__ __forceinline__ void mma16816(float* d, const uint32_t* a,
                                         uint32_t b0, uint32_t b1) {
    asm volatile(
        "mma.sync.aligned.m16n8k16.row.col.f32.f16.f16.f32 "
        "{%0,%1,%2,%3}, {%4,%5,%6,%7}, {%8,%9}, {%0,%1,%2,%3};\n"
        : "+f"(d[0]), "+f"(d[1]), "+f"(d[2]), "+f"(d[3])
        : "r"(a[0]), "r"(a[1]), "r"(a[2]), "r"(a[3]), "r"(b0), "r"(b1));
}
__device__ __forceinline__ uint32_t packh2(float x, float y) {
    __half2 h = __floats2half2_rn(x, y);
    return *reinterpret_cast<uint32_t*>(&h);
}

// ---------------- 0) fp32 -> fp16 weight conversion --------------------------
__global__ void k_convert_h(const float* __restrict__ in, __half* __restrict__ out,
                            size_t n8) {
    const float4* in4 = reinterpret_cast<const float4*>(in);
    uint4* out4 = reinterpret_cast<uint4*>(out);
    for (size_t i = (size_t)blockIdx.x * 256 + threadIdx.x; i < n8;
         i += (size_t)gridDim.x * 256) {
        float4 a = in4[2 * i], b = in4[2 * i + 1];
        __half2 h0 = __floats2half2_rn(a.x, a.y);
        __half2 h1 = __floats2half2_rn(a.z, a.w);
        __half2 h2 = __floats2half2_rn(b.x, b.y);
        __half2 h3 = __floats2half2_rn(b.z, b.w);
        uint4 o;
        o.x = *reinterpret_cast<unsigned*>(&h0);
        o.y = *reinterpret_cast<unsigned*>(&h1);
        o.z = *reinterpret_cast<unsigned*>(&h2);
        o.w = *reinterpret_cast<unsigned*>(&h3);
        out4[i] = o;
    }
}

// ---------------- 1) mod = silu(vec) @ mod_w + mod_b ------------------------
__global__ void k_mod_gemv(const float* __restrict__ vec,
                           const float* __restrict__ mw,
                           const float* __restrict__ mb) {
    __shared__ float sv[HID];
    int tid = threadIdx.x;
    for (int i = tid; i < HID; i += 256) {
        float v = vec[i];
        sv[i] = v / (1.f + expf(-v));
    }
    __syncthreads();
    int j = tid & 63, ky = tid >> 6;
    int col = blockIdx.x * 64 + j;
    const float* wp = mw + col;
    float acc = 0.f;
    int i0 = ky * 768;
#pragma unroll 4
    for (int i = i0; i < i0 + 768; ++i)
        acc += sv[i] * wp[(size_t)i * (3 * HID)];
    __shared__ float red[4][64];
    red[ky][j] = acc;
    __syncthreads();
    if (ky == 0)
        g_mod[col] = red[0][j] + red[1][j] + red[2][j] + red[3][j] + mb[col];
}

// ---------------- 2) LayerNorm + modulate (writes fp16) ----------------------
__global__ void k_ln_mod(const float* __restrict__ x,
                         const float* __restrict__ gamma,
                         const float* __restrict__ beta) {
    int l = blockIdx.x;
    const float* xr = x + (size_t)l * HID;
    float s = 0.f, ss = 0.f;
    for (int c = threadIdx.x; c < HID; c += 256) {
        float v = xr[c];
        s += v; ss += v * v;
    }
    __shared__ float rs[8], rss[8];
    for (int o = 16; o > 0; o >>= 1) {
        s  += __shfl_xor_sync(~0u, s, o);
        ss += __shfl_xor_sync(~0u, ss, o);
    }
    int w = threadIdx.x >> 5;
    if ((threadIdx.x & 31) == 0) { rs[w] = s; rss[w] = ss; }
    __syncthreads();
    float S = 0.f, SS = 0.f;
#pragma unroll
    for (int i = 0; i < 8; ++i) { S += rs[i]; SS += rss[i]; }
    float mu   = S * (1.f / HID);
    float var  = SS * (1.f / HID) - mu * mu;
    float rstd = rsqrtf(var + 1e-6f);
    __half* o = g_xmod + (size_t)l * HID;
    for (int c = threadIdx.x; c < HID; c += 256) {
        float ln = (xr[c] - mu) * rstd * gamma[c] + beta[c];
        o[c] = __float2half_rn((1.f + g_mod[HID + c]) * ln + g_mod[c]);
    }
}

// ---------------- FP16 GEMM: raw mma + ldmatrix, 128x128, BK=32, 3-stage -----
// mode 0: C = A@B + b1 with FUSED per-tile epilogue:
//   cols in q/k region -> rmsnorm(row over 128) + rope -> g_q/g_k ([H][L][D])
//   cols in v region   -> g_v
//   cols >= QKVN       -> gelu -> g_cat
// mode 2: split-K partial: raw acc (no bias) -> f_out + blockIdx.z*LSEQ*HID
#define BM 128
#define BN 128
#define BK 32
#define NSTG 3
#define AS_H 40
#define BS_H 136
#define STG_A (BM * AS_H)
#define STG_B (BK * BS_H)
#define GEMM_DSMEM (NSTG * (STG_A + STG_B) * 2)

__global__ void __launch_bounds__(256, 2) k_gemm(
    const __half* __restrict__ A, int lda,
    const __half* __restrict__ B, int ldb, int K,
    const float* __restrict__ bias, int mode,
    float* __restrict__ f_out,
    const float* __restrict__ pe,
    const float* __restrict__ qs,
    const float* __restrict__ ks) {
    extern __shared__ __half hsm[];
    __shared__ float red2[2][128];

    int tid = threadIdx.x;
    int m0 = blockIdx.x * BM, n0 = blockIdx.y * BN;
    if (mode == 2) {
        int kz = blockIdx.z;
        A += (size_t)kz * KSPLIT;
        B += (size_t)kz * KSPLIT * ldb;
        f_out += (size_t)kz * LSEQ * HID;
    }
    int w = tid >> 5, lane = tid & 31;
    int wm = w & 3, wn = w >> 2;   // warp tile 32x64

    int ar = tid >> 1, ac = (tid & 1) * 16;
    int br = tid >> 3, bc = (tid & 7) * 16;

    int lm = lane >> 3, lr = lane & 7;
    int fr = lane >> 2, fc = (lane & 3) * 2;

    float acc[2][8][4];
#pragma unroll
    for (int i = 0; i < 2; ++i)
#pragma unroll
        for (int c = 0; c < 8; ++c)
#pragma unroll
            for (int j = 0; j < 4; ++j) acc[i][c][j] = 0.f;

    int nsteps = K / BK;
    auto issue = [&](int s) {
        int k0 = s * BK;
        __half* As = hsm + (s % NSTG) * (STG_A + STG_B);
        __half* Bs = As + STG_A;
        {
            const __half* src = A + (size_t)(m0 + ar) * lda + k0 + ac;
            unsigned dst = saddr(As + ar * AS_H + ac);
            cp16(dst, src);
            cp16(dst + 16, src + 8);
        }
        {
            const __half* src = B + (size_t)(k0 + br) * ldb + n0 + bc;
            unsigned dst = saddr(Bs + br * BS_H + bc);
            cp16(dst, src);
            cp16(dst + 16, src + 8);
        }
    };

    issue(0); cp_commit();
    issue(1); cp_commit();

    for (int s = 0; s < nsteps; ++s) {
        if (s + 1 < nsteps) cp_wait1(); else cp_wait0();
        __syncthreads();
        if (s + 2 < nsteps) { issue(s + 2); cp_commit(); }
        __half* As = hsm + (s % NSTG) * (STG_A + STG_B);
        __half* Bs = As + STG_A;
        unsigned abase = saddr(As), bbase = saddr(Bs);
#pragma unroll
        for (int kt = 0; kt < 2; ++kt) {
            int kk = kt * 16;
            uint32_t a[2][4];
#pragma unroll
            for (int i = 0; i < 2; ++i) {
                unsigned addr = abase +
                    ((wm * 32 + i * 16 + (lm & 1) * 8 + lr) * AS_H + kk + (lm >> 1) * 8) * 2;
                ldsm4(a[i][0], a[i][1], a[i][2], a[i][3], addr);
            }
            uint32_t b[8][2];
#pragma unroll
            for (int bw = 0; bw < 4; ++bw) {
                unsigned addr = bbase +
                    ((kk + (lm & 1) * 8 + lr) * BS_H + wn * 64 + bw * 16 + (lm >> 1) * 8) * 2;
                uint32_t r0, r1, r2, r3;
                ldsm4t(r0, r1, r2, r3, addr);
                b[2 * bw][0] = r0; b[2 * bw][1] = r1;
                b[2 * bw + 1][0] = r2; b[2 * bw + 1][1] = r3;
            }
#pragma unroll
            for (int i = 0; i < 2; ++i)
#pragma unroll
                for (int c = 0; c < 8; ++c)
                    mma16816(acc[i][c], a[i], b[c][0], b[c][1]);
        }
    }

    // -------- epilogues --------
    if (mode == 2) {
#pragma unroll
        for (int i = 0; i < 2; ++i) {
            int gm0 = m0 + wm * 32 + i * 16 + fr;
            int gm1 = gm0 + 8;
#pragma unroll
            for (int c = 0; c < 8; ++c) {
                int gn = n0 + wn * 64 + c * 8 + fc;
                float2 o0 = {acc[i][c][0], acc[i][c][1]};
                float2 o1 = {acc[i][c][2], acc[i][c][3]};
                *reinterpret_cast<float2*>(&f_out[(size_t)gm0 * HID + gn]) = o0;
                *reinterpret_cast<float2*>(&f_out[(size_t)gm1 * HID + gn]) = o1;
            }
        }
        return;
    }

    // add bias (uniform path for mode 0)
#pragma unroll
    for (int i = 0; i < 2; ++i)
#pragma unroll
        for (int c = 0; c < 8; ++c) {
            int gn = n0 + wn * 64 + c * 8 + fc;
            float b0 = bias[gn], b1 = bias[gn + 1];
            acc[i][c][0] += b0; acc[i][c][1] += b1;
            acc[i][c][2] += b0; acc[i][c][3] += b1;
        }

    if (n0 >= QKVN) {
        // gelu -> g_cat
#pragma unroll
        for (int i = 0; i < 2; ++i) {
            int gm0 = m0 + wm * 32 + i * 16 + fr;
            int gm1 = gm0 + 8;
#pragma unroll
            for (int c = 0; c < 8; ++c) {
                int gn = n0 + wn * 64 + c * 8 + fc;
                float v00 = acc[i][c][0], v01 = acc[i][c][1];
                float v10 = acc[i][c][2], v11 = acc[i][c][3];
                float t, g;
                t = 0.7978845608028654f * (v00 + 0.044715f * v00 * v00 * v00);
                g = 0.5f * v00 * (1.f + tanhf(t)); v00 = g;
                t = 0.7978845608028654f * (v01 + 0.044715f * v01 * v01 * v01);
                g = 0.5f * v01 * (1.f + tanhf(t)); v01 = g;
                t = 0.7978845608028654f * (v10 + 0.044715f * v10 * v10 * v10);
                g = 0.5f * v10 * (1.f + tanhf(t)); v10 = g;
                t = 0.7978845608028654f * (v11 + 0.044715f * v11 * v11 * v11);
                g = 0.5f * v11 * (1.f + tanhf(t)); v11 = g;
                int col = HID + (gn - QKVN);
                *reinterpret_cast<uint32_t*>(&g_cat[(size_t)gm0 * CATN + col]) = packh2(v00, v01);
                *reinterpret_cast<uint32_t*>(&g_cat[(size_t)gm1 * CATN + col]) = packh2(v10, v11);
            }
        }
        return;
    }

    // fused qkv epilogue: this N-tile is exactly one head of q, k, or v
    int region = n0 / HID;               // 0=q, 1=k, 2=v
    int hh = (n0 % HID) / HD;            // head index

    if (region == 2) {
#pragma unroll
        for (int i = 0; i < 2; ++i) {
            int gm0 = m0 + wm * 32 + i * 16 + fr;
            int gm1 = gm0 + 8;
#pragma unroll
            for (int c = 0; c < 8; ++c) {
                int d = wn * 64 + c * 8 + fc;
                *reinterpret_cast<uint32_t*>(&g_v[((size_t)hh * LSEQ + gm0) * HD + d]) =
                    packh2(acc[i][c][0], acc[i][c][1]);
                *reinterpret_cast<uint32_t*>(&g_v[((size_t)hh * LSEQ + gm1) * HD + d]) =
                    packh2(acc[i][c][2], acc[i][c][3]);
            }
        }
        return;
    }

    // q/k: rmsnorm over the row's 128 cols (all in this tile) + rope
    float ss[2][2] = {{0.f, 0.f}, {0.f, 0.f}};
#pragma unroll
    for (int i = 0; i < 2; ++i)
#pragma unroll
        for (int c = 0; c < 8; ++c) {
            ss[i][0] += acc[i][c][0] * acc[i][c][0] + acc[i][c][1] * acc[i][c][1];
            ss[i][1] += acc[i][c][2] * acc[i][c][2] + acc[i][c][3] * acc[i][c][3];
        }
#pragma unroll
    for (int i = 0; i < 2; ++i) {
        ss[i][0] += __shfl_xor_sync(~0u, ss[i][0], 1);
        ss[i][0] += __shfl_xor_sync(~0u, ss[i][0], 2);
        ss[i][1] += __shfl_xor_sync(~0u, ss[i][1], 1);
        ss[i][1] += __shfl_xor_sync(~0u, ss[i][1], 2);
    }
    if ((lane & 3) == 0) {
#pragma unroll
        for (int i = 0; i < 2; ++i) {
            red2[wn][wm * 32 + i * 16 + fr]     = ss[i][0];
            red2[wn][wm * 32 + i * 16 + fr + 8] = ss[i][1];
        }
    }
    __syncthreads();

    const float* scale = (region == 0) ? qs : ks;
    __half* outp = (region == 0) ? g_q : g_k;
    float extra = (region == 0) ? 0.08838834764831845f : 1.f;
#pragma unroll
    for (int i = 0; i < 2; ++i) {
        int r0 = wm * 32 + i * 16 + fr;
        int gm0 = m0 + r0, gm1 = gm0 + 8;
        float rstd0 = rsqrtf((red2[0][r0] + red2[1][r0]) * (1.f / HD) + 1e-6f);
        float rstd1 = rsqrtf((red2[0][r0 + 8] + red2[1][r0 + 8]) * (1.f / HD) + 1e-6f);
#pragma unroll
        for (int c = 0; c < 8; ++c) {
            int d = wn * 64 + c * 8 + fc;
            float s0 = scale[d], s1 = scale[d + 1];
            float v00 = acc[i][c][0] * rstd0 * s0, v01 = acc[i][c][1] * rstd0 * s1;
            float v10 = acc[i][c][2] * rstd1 * s0, v11 = acc[i][c][3] * rstd1 * s1;
            int cidx = d >> 1;
            float4 p0 = *reinterpret_cast<const float4*>(pe + ((size_t)gm0 * 64 + cidx) * 4);
            float4 p1 = *reinterpret_cast<const float4*>(pe + ((size_t)gm1 * 64 + cidx) * 4);
            float e0 = (p0.x * v00 + p0.y * v01) * extra;
            float o0 = (p0.z * v00 + p0.w * v01) * extra;
            float e1 = (p1.x * v10 + p1.y * v11) * extra;
            float o1 = (p1.z * v10 + p1.w * v11) * extra;
            *reinterpret_cast<uint32_t*>(&outp[((size_t)hh * LSEQ + gm0) * HD + d]) = packh2(e0, o0);
            *reinterpret_cast<uint32_t*>(&outp[((size_t)hh * LSEQ + gm1) * HD + d]) = packh2(e1, o1);
        }
    }
}

// ---------------- split-K reduce: out = resid + gate * (p0+p1+p2 + bias) -----
__global__ void k_reduce(float* __restrict__ out,
                         const float* __restrict__ resid,
                         const float* __restrict__ gate,
                         const float* __restrict__ bias) {
    size_t i = (size_t)blockIdx.x * 256 + threadIdx.x;   // float4 index
    size_t total = (size_t)LSEQ * HID / 4;
    if (i >= total) return;
    int col = (int)((i * 4) % HID);
    const float4 p0 = reinterpret_cast<const float4*>(g_part)[i];
    const float4 p1 = reinterpret_cast<const float4*>(g_part + (size_t)LSEQ * HID)[i];
    const float4 p2 = reinterpret_cast<const float4*>(g_part + (size_t)2 * LSEQ * HID)[i];
    float4 r = reinterpret_cast<const float4*>(resid)[i];
    float4 bb = *reinterpret_cast<const float4*>(&bias[col]);
    float4 gg = *reinterpret_cast<const float4*>(&gate[col]);
    float4 o;
    o.x = r.x + gg.x * (p0.x + p1.x + p2.x + bb.x);
    o.y = r.y + gg.y * (p0.y + p1.y + p2.y + bb.y);
    o.z = r.z + gg.z * (p0.z + p1.z + p2.z + bb.z);
    o.w = r.w + gg.w * (p0.w + p1.w + p2.w + bb.w);
    reinterpret_cast<float4*>(out)[i] = o;
}

// ---------------- 4) flash attention: 128 q rows/CTA, 8 warps ----------------
#define KS_H 136
#define FA_BUF (64 * KS_H)
#define FA_NSTG 3
#define FA_DSMEM (FA_NSTG * 2 * FA_BUF * 2)
#define NKT (LSEQ / 64)

__global__ void __launch_bounds__(256, 1) k_fattn() {
    extern __shared__ __half fsm[];
    int tid = threadIdx.x, w = tid >> 5, lane = tid & 31;
    int hh = blockIdx.y;
    int q0 = blockIdx.x * 128;
    const __half* Qg = g_q + ((size_t)hh * LSEQ + q0 + w * 16) * HD;
    const __half* Kg = g_k + (size_t)hh * LSEQ * HD;
    const __half* Vg = g_v + (size_t)hh * LSEQ * HD;

    int fr = lane >> 2;
    int fc = (lane & 3) * 2;
    uint32_t qa[8][4];
#pragma unroll
    for (int kc = 0; kc < 8; ++kc) {
        qa[kc][0] = *reinterpret_cast<const uint32_t*>(&Qg[(size_t)fr * HD + kc * 16 + fc]);
        qa[kc][1] = *reinterpret_cast<const uint32_t*>(&Qg[(size_t)(fr + 8) * HD + kc * 16 + fc]);
        qa[kc][2] = *reinterpret_cast<const uint32_t*>(&Qg[(size_t)fr * HD + kc * 16 + 8 + fc]);
        qa[kc][3] = *reinterpret_cast<const uint32_t*>(&Qg[(size_t)(fr + 8) * HD + kc * 16 + 8 + fc]);
    }

    float o[16][4];
#pragma unroll
    for (int c = 0; c < 16; ++c)
#pragma unroll
        for (int j = 0; j < 4; ++j) o[c][j] = 0.f;
    float m0 = -1e30f, m1 = -1e30f, l0 = 0.f, l1 = 0.f;

    int sr = tid >> 2, sc = (tid & 3) * 32;
    auto stg = [&](int t) {
        __half* Ks = fsm + (t % FA_NSTG) * 2 * FA_BUF;
        __half* Vs = Ks + FA_BUF;
        const __half* ksrc = Kg + (size_t)(t * 64 + sr) * HD + sc;
        unsigned kd = saddr(Ks + sr * KS_H + sc);
#pragma unroll
        for (int p = 0; p < 4; ++p) cp16(kd + p * 16, ksrc + p * 8);
        const __half* vsrc = Vg + (size_t)(t * 64 + sr) * HD + sc;
        unsigned vd = saddr(Vs + sr * KS_H + sc);
#pragma unroll
        for (int p = 0; p < 4; ++p) cp16(vd + p * 16, vsrc + p * 8);
    };

    stg(0); cp_commit();
    stg(1); cp_commit();

    int lm = lane >> 3, lr = lane & 7;

    for (int t = 0; t < NKT; ++t) {
        if (t + 1 < NKT) cp_wait1(); else cp_wait0();
        __syncthreads();
        if (t + 2 < NKT) { stg(t + 2); cp_commit(); }
        __half* Ks = fsm + (t % FA_NSTG) * 2 * FA_BUF;
        __half* Vs = Ks + FA_BUF;
        unsigned kbase = saddr(Ks), vbase = saddr(Vs);

        float s[8][4];
#pragma unroll
        for (int c = 0; c < 8; ++c)
#pragma unroll
            for (int j = 0; j < 4; ++j) s[c][j] = 0.f;
#pragma unroll
        for (int kc = 0; kc < 8; ++kc) {
#pragma unroll
            for (int cp = 0; cp < 4; ++cp) {
                unsigned addr = kbase +
                    (((2 * cp + (lm >> 1)) * 8 + lr) * KS_H + kc * 16 + (lm & 1) * 8) * 2;
                uint32_t b0, b1, b2, b3;
                ldsm4(b0, b1, b2, b3, addr);
                mma16816(s[2 * cp], qa[kc], b0, b1);
                mma16816(s[2 * cp + 1], qa[kc], b2, b3);
            }
        }

        float t0 = -1e30f, t1 = -1e30f;
#pragma unroll
        for (int c = 0; c < 8; ++c) {
            t0 = fmaxf(t0, fmaxf(s[c][0], s[c][1]));
            t1 = fmaxf(t1, fmaxf(s[c][2], s[c][3]));
        }
        t0 = fmaxf(t0, __shfl_xor_sync(~0u, t0, 1));
        t0 = fmaxf(t0, __shfl_xor_sync(~0u, t0, 2));
        t1 = fmaxf(t1, __shfl_xor_sync(~0u, t1, 1));
        t1 = fmaxf(t1, __shfl_xor_sync(~0u, t1, 2));
        float mn0 = fmaxf(m0, t0), mn1 = fmaxf(m1, t1);
        float sc0 = __expf(m0 - mn0), sc1 = __expf(m1 - mn1);
        m0 = mn0; m1 = mn1;
        uint32_t ph[8][2];
        float ps0 = 0.f, ps1 = 0.f;
#pragma unroll
        for (int c = 0; c < 8; ++c) {
            float e0 = __expf(s[c][0] - mn0);
            float e1 = __expf(s[c][1] - mn0);
            float e2 = __expf(s[c][2] - mn1);
            float e3 = __expf(s[c][3] - mn1);
            ps0 += e0 + e1; ps1 += e2 + e3;
            ph[c][0] = packh2(e0, e1);
            ph[c][1] = packh2(e2, e3);
        }
        l0 = l0 * sc0 + ps0;
        l1 = l1 * sc1 + ps1;
#pragma unroll
        for (int c = 0; c < 16; ++c) {
            o[c][0] *= sc0; o[c][1] *= sc0;
            o[c][2] *= sc1; o[c][3] *= sc1;
        }

#pragma unroll
        for (int kg = 0; kg < 4; ++kg) {
            uint32_t pa[4] = {ph[2 * kg][0], ph[2 * kg][1],
                              ph[2 * kg + 1][0], ph[2 * kg + 1][1]};
#pragma unroll
            for (int cp = 0; cp < 8; ++cp) {
                unsigned addr = vbase +
                    ((kg * 16 + (lm & 1) * 8 + lr) * KS_H + (2 * cp + (lm >> 1)) * 8) * 2;
                uint32_t b0, b1, b2, b3;
                ldsm4t(b0, b1, b2, b3, addr);
                mma16816(o[2 * cp], pa, b0, b1);
                mma16816(o[2 * cp + 1], pa, b2, b3);
            }
        }
    }

    l0 += __shfl_xor_sync(~0u, l0, 1);
    l0 += __shfl_xor_sync(~0u, l0, 2);
    l1 += __shfl_xor_sync(~0u, l1, 1);
    l1 += __shfl_xor_sync(~0u, l1, 2);
    float il0 = 1.f / l0, il1 = 1.f / l1;
    int row0 = q0 + w * 16 + fr;
    int row1 = row0 + 8;
#pragma unroll
    for (int c = 0; c < 16; ++c) {
        int col = hh * HD + c * 8 + fc;
        *reinterpret_cast<uint32_t*>(&g_cat[(size_t)row0 * CATN + col]) =
            packh2(o[c][0] * il0, o[c][1] * il0);
        *reinterpret_cast<uint32_t*>(&g_cat[(size_t)row1 * CATN + col]) =
            packh2(o[c][2] * il1, o[c][3] * il1);
    }
}

// ---------------- launch -----------------------------------------------------
extern "C" void kernel_launch(void* const* d_in, const int* in_sizes, int n_in,
                              void* d_out, int out_size) {
    const float* x     = (const float*)d_in[0];
    const float* vec   = (const float*)d_in[1];
    const float* pe    = (const float*)d_in[2];
    const float* mod_w = (const float*)d_in[3];
    const float* mod_b = (const float*)d_in[4];
    const float* ln_g  = (const float*)d_in[5];
    const float* ln_b  = (const float*)d_in[6];
    const float* w1    = (const float*)d_in[7];
    const float* b1    = (const float*)d_in[8];
    const float* q_s   = (const float*)d_in[9];
    const float* k_s   = (const float*)d_in[10];
    const float* w2    = (const float*)d_in[11];
    const float* b2    = (const float*)d_in[12];
    float* out = (float*)d_out;

    __half *p_xmod, *p_cat, *p_w1h, *p_w2h;
    float *p_mod, *p_part;
    cudaGetSymbolAddress((void**)&p_xmod, g_xmod);
    cudaGetSymbolAddress((void**)&p_cat,  g_cat);
    cudaGetSymbolAddress((void**)&p_mod,  g_mod);
    cudaGetSymbolAddress((void**)&p_w1h,  g_w1h);
    cudaGetSymbolAddress((void**)&p_w2h,  g_w2h);
    cudaGetSymbolAddress((void**)&p_part, g_part);

    cudaFuncSetAttribute(k_fattn, cudaFuncAttributeMaxDynamicSharedMemorySize,
                         FA_DSMEM);
    cudaFuncSetAttribute(k_gemm, cudaFuncAttributeMaxDynamicSharedMemorySize,
                         GEMM_DSMEM);

    k_mod_gemv<<<144, 256>>>(vec, mod_w, mod_b);                       // 1
    k_convert_h<<<4096, 256>>>(w1, p_w1h, (size_t)HID * W1N / 8);      // 2
    k_ln_mod<<<LSEQ, 256>>>(x, ln_g, ln_b);                            // 3
    // fused: h = x_mod @ w1 + b1, q/k rmsnorm+rope, v, gelu   (launch #4)
    k_gemm<<<dim3(16, 168), 256, GEMM_DSMEM>>>(
        p_xmod, HID, p_w1h, W1N, HID, b1, 0, nullptr, pe, q_s, k_s);
    k_fattn<<<dim3(LSEQ / 128, NH), 256, FA_DSMEM>>>();                // 5
    k_convert_h<<<4096, 256>>>(w2, p_w2h, (size_t)CATN * HID / 8);     // 6
    // split-K=3 partials for cat @ w2
    k_gemm<<<dim3(16, 24, SPLITK), 256, GEMM_DSMEM>>>(
        p_cat, CATN, p_w2h, HID, KSPLIT, nullptr, 2, p_part,
        nullptr, nullptr, nullptr);
    // out = x + gate * (sum parts + b2)
    k_reduce<<<(LSEQ * HID / 4 + 255) / 256, 256>>>(out, x, p_mod + 2 * HID, b2);
    (void)in_sizes; (void)n_in; (void)out_size;
}